// round 7
// baseline (speedup 1.0000x reference)
#include <cuda_runtime.h>
#include <math.h>

#define NCH 256
#define TW 16
#define TH 4
#define OCT 64
#define CB 16
#define WPAD 68   // padded oc dim for weight smem; tap stride 272B (16B-aligned)
#define IRS2 18   // input row stride in float2 (144B, 16B-aligned)

#define SW_FLOATS (CB*9*WPAD)                  // 9792 floats = 39168 B
#define SW_BYTES  (SW_FLOATS*4)
#define SIN_BYTES (CB*(TH+2)*IRS2*8)           // 13824 B
#define SMEM_TOTAL (SW_BYTES + SIN_BYTES)      // 52992 B

// Scratch (static device globals; allocation is forbidden)
__device__ float g_buf0[8u*256u*64u*64u];   // 33.5 MB
__device__ float g_buf1[8u*256u*64u*64u];   // 33.5 MB
__device__ float g_head[8u*720u*64u*64u];   // 94.4 MB

typedef unsigned long long ull;

// packed f32x2 ops (Blackwell FFMA2 path — ptxas never emits from C++)
#define FMA2(D, A, B) asm("fma.rn.f32x2 %0, %1, %2, %0;" : "+l"(D) : "l"(A), "l"(B))
#define ADD2(D, A, B) asm("add.rn.f32x2 %0, %1, %2;" : "=l"(D) : "l"(A), "l"(B))
// D = A - B  via  A + (B ^ signmask)  (IEEE-identical to subtraction)
#define NSUB2(D, A, B) do { ull _nb; \
    asm("xor.b64 %0, %1, 0x8000000080000000;" : "=l"(_nb) : "l"(B)); \
    ADD2(D, A, _nb); } while(0)

__device__ __forceinline__ float plo(ull v){ return __uint_as_float((unsigned)v); }
__device__ __forceinline__ float phi(ull v){ return __uint_as_float((unsigned)(v>>32)); }

// One input channel (9 taps), packed: ACC[p][i] accumulates oc-pair p, pixel i.
// Inputs come pre-duplicated (v,v) from smem; weights pre-paired in smem.
#define CHANNEL9P(ACC, CI) \
    _Pragma("unroll") \
    for (int ky = 0; ky < 3; ky++) { \
        const ulonglong2* ib = (const ulonglong2*)(s_in2 + ((CI)*(TH+2) + py+ky)*IRS2 + px); \
        const ulonglong2 p0 = ib[0], p1 = ib[1], p2 = ib[2]; /* (a0,a0)..(a5,a5) */ \
        { const ulonglong2 wv = *(const ulonglong2*)&s_w[((CI)*9 + ky*3 + 0)*WPAD + (og<<2)]; \
          FMA2(ACC[0][0], wv.x, p0.x); FMA2(ACC[0][1], wv.x, p0.y); FMA2(ACC[0][2], wv.x, p1.x); FMA2(ACC[0][3], wv.x, p1.y); \
          FMA2(ACC[1][0], wv.y, p0.x); FMA2(ACC[1][1], wv.y, p0.y); FMA2(ACC[1][2], wv.y, p1.x); FMA2(ACC[1][3], wv.y, p1.y); } \
        { const ulonglong2 wv = *(const ulonglong2*)&s_w[((CI)*9 + ky*3 + 1)*WPAD + (og<<2)]; \
          FMA2(ACC[0][0], wv.x, p0.y); FMA2(ACC[0][1], wv.x, p1.x); FMA2(ACC[0][2], wv.x, p1.y); FMA2(ACC[0][3], wv.x, p2.x); \
          FMA2(ACC[1][0], wv.y, p0.y); FMA2(ACC[1][1], wv.y, p1.x); FMA2(ACC[1][2], wv.y, p1.y); FMA2(ACC[1][3], wv.y, p2.x); } \
        { const ulonglong2 wv = *(const ulonglong2*)&s_w[((CI)*9 + ky*3 + 2)*WPAD + (og<<2)]; \
          FMA2(ACC[0][0], wv.x, p1.x); FMA2(ACC[0][1], wv.x, p1.y); FMA2(ACC[0][2], wv.x, p2.x); FMA2(ACC[0][3], wv.x, p2.y); \
          FMA2(ACC[1][0], wv.y, p1.x); FMA2(ACC[1][1], wv.y, p1.y); FMA2(ACC[1][2], wv.y, p2.x); FMA2(ACC[1][3], wv.y, p2.y); } \
    }

// ---------------------------------------------------------------------------
// 3x3 SAME conv, C_in=256, OC generic, optional ReLU. Packed-f32x2 inner loop.
// Block: 256 threads -> [64 oc x 64 px]; thread: 2 oc-pairs x 4 px (packed).
// KAHAN=true (cls): compensated 4-channel folds (class_id argmax tie-safety).
// ---------------------------------------------------------------------------
template<bool KAHAN>
__global__ __launch_bounds__(256) void conv3x3_k(
    const float* __restrict__ in, const float* __restrict__ wt,
    const float* __restrict__ bias, float* __restrict__ out,
    int OC, int H, int W, int tilesX, int relu)
{
    extern __shared__ __align__(16) unsigned char smem_raw[];
    float*  s_w   = (float*)smem_raw;                     // [CB*9*WPAD]
    float2* s_in2 = (float2*)(smem_raw + SW_BYTES);       // [CB][TH+2][IRS2], (v,v)

    const int t   = threadIdx.x;
    const int tX  = blockIdx.x % tilesX;
    const int tY  = blockIdx.x / tilesX;
    const int oc0 = blockIdx.y * OCT;
    const int b   = blockIdx.z;
    const int og  = t & 15;
    const int pg  = t >> 4;
    const int px  = (pg & 3) << 2;
    const int py  = pg >> 2;
    const int gx0 = tX * TW, gy0 = tY * TH;

    // weight staging: 4 threads per oc, 9 x LDG.128 each
    const int w_oc = t >> 2;
    const int w_q  = t & 3;
    const int w_goc = oc0 + w_oc;
    const bool w_ok = (w_goc < OC);
    const float* wbase = wt + (size_t)(w_ok ? w_goc : 0) * (NCH*9);

    ull acc[2][4], cmp[2][4];
    #pragma unroll
    for (int p = 0; p < 2; p++)
        #pragma unroll
        for (int i = 0; i < 4; i++) { acc[p][i] = 0ull; cmp[p][i] = 0ull; }

    const float* inb = in + (size_t)b * NCH * H * W;

    for (int cb = 0; cb < NCH; cb += CB) {
        __syncthreads();
        // ---- stage input tile, duplicated (v,v), halo zero-padded ----
        #pragma unroll 2
        for (int i = t; i < CB*(TH+2)*(TW+2); i += 256) {
            int ci  = i / ((TH+2)*(TW+2));
            int rem = i - ci*((TH+2)*(TW+2));
            int r   = rem / (TW+2);
            int c   = rem - r*(TW+2);
            int gy  = gy0 + r - 1;
            int gx  = gx0 + c - 1;
            float v = 0.f;
            if ((unsigned)gy < (unsigned)H && (unsigned)gx < (unsigned)W)
                v = inb[((size_t)(cb+ci)*H + gy)*W + gx];
            s_in2[(ci*(TH+2) + r)*IRS2 + c] = make_float2(v, v);
        }
        // ---- stage weights: s_w[(ci*9+tap)*WPAD + oc] ----
        {
            const float* wp = wbase + (size_t)cb*9;
            #pragma unroll
            for (int k = 0; k < 9; k++) {
                int j0 = w_q*4 + k*16;
                float4 wv = make_float4(0.f, 0.f, 0.f, 0.f);
                if (w_ok) wv = *(const float4*)&wp[j0];
                s_w[(j0+0)*WPAD + w_oc] = wv.x;
                s_w[(j0+1)*WPAD + w_oc] = wv.y;
                s_w[(j0+2)*WPAD + w_oc] = wv.z;
                s_w[(j0+3)*WPAD + w_oc] = wv.w;
            }
        }
        __syncthreads();

        if (KAHAN) {
            #pragma unroll 1
            for (int cig = 0; cig < CB; cig += 4) {
                ull tt[2][4];
                #pragma unroll
                for (int p = 0; p < 2; p++)
                    #pragma unroll
                    for (int i = 0; i < 4; i++) tt[p][i] = 0ull;

                #pragma unroll
                for (int cc = 0; cc < 4; cc++) {
                    const int ci = cig + cc;
                    CHANNEL9P(tt, ci)
                }
                // compensated fold (per packed lane, IEEE-identical to scalar)
                #pragma unroll
                for (int p = 0; p < 2; p++) {
                    #pragma unroll
                    for (int i = 0; i < 4; i++) {
                        ull y, s, d;
                        NSUB2(y, tt[p][i], cmp[p][i]);
                        ADD2(s, acc[p][i], y);
                        NSUB2(d, s, acc[p][i]);
                        NSUB2(cmp[p][i], d, y);
                        acc[p][i] = s;
                    }
                }
            }
        } else {
            #pragma unroll 4
            for (int ci = 0; ci < CB; ci++) {
                CHANNEL9P(acc, ci)
            }
        }
    }

    int gy = gy0 + py;
    if (gy >= H) return;
    #pragma unroll
    for (int p = 0; p < 2; p++) {
        #pragma unroll
        for (int half = 0; half < 2; half++) {
            int goc = oc0 + og*4 + p*2 + half;
            if (goc >= OC) continue;
            float bv = bias[goc];
            #pragma unroll
            for (int i = 0; i < 4; i++) {
                int gx = gx0 + px + i;
                if (gx >= W) continue;
                float a = half ? phi(acc[p][i]) : plo(acc[p][i]);
                float v;
                if (KAHAN) {
                    float c = half ? phi(cmp[p][i]) : plo(cmp[p][i]);
                    v = (a - c) + bv;
                } else {
                    v = a + bv;
                }
                if (relu) v = fmaxf(v, 0.f);
                out[((size_t)b*OC + goc)*H*W + (size_t)gy*W + gx] = v;
            }
        }
    }
}

// ---------------------------------------------------------------------------
// cls epilogue: head [B,720,H,W] -> scores + class_id (argmax on logits).
// ---------------------------------------------------------------------------
__global__ void cls_reduce_k(const float* __restrict__ head,
                             float* __restrict__ scores, float* __restrict__ cls_id,
                             int H, int W, int Aoff, int Atot, int total)
{
    int idx = blockIdx.x * blockDim.x + threadIdx.x;
    if (idx >= total) return;
    int HW  = H * W;
    int pos = idx % HW;
    int tmp = idx / HW;
    int a   = tmp % 9;
    int b   = tmp / 9;
    const float* p = head + ((size_t)b*720 + (size_t)a*80) * HW + pos;
    float best = p[0];
    int   bi   = 0;
    #pragma unroll 4
    for (int k = 1; k < 80; k++) {
        float v = p[(size_t)k * HW];
        if (v > best) { best = v; bi = k; }
    }
    size_t o = (size_t)b*Atot + Aoff + (size_t)pos*9 + a;
    scores[o] = 1.f / (1.f + expf(-best));
    cls_id[o] = (float)bi;
}

// ---------------------------------------------------------------------------
// reg epilogue: head [B,36,H,W] -> decoded boxes, analytic anchors.
// ---------------------------------------------------------------------------
__global__ void reg_decode_k(const float* __restrict__ head, float* __restrict__ boxes,
                             int H, int W, int stride, int Aoff, int Atot, int total)
{
    int idx = blockIdx.x * blockDim.x + threadIdx.x;
    if (idx >= total) return;
    int HW  = H * W;
    int pos = idx % HW;
    int tmp = idx / HW;
    int a   = tmp % 9;
    int b   = tmp / 9;
    int x   = pos % W, y = pos / W;

    const float* p = head + ((size_t)b*36 + (size_t)a*4) * HW + pos;
    float d0 = p[0], d1 = p[HW], d2 = p[2*(size_t)HW], d3 = p[3*(size_t)HW];

    float s     = (float)stride;
    int   ridx  = a / 3, sidx = a - ridx*3;
    float ratio = (ridx == 0) ? 0.5f : ((ridx == 1) ? 1.f : 2.f);
    float scale = (sidx == 0) ? 1.f : ((sidx == 1) ? 1.2599210498948732f : 1.5874010519681994f);
    float w0 = 4.f * s * scale;
    float aw = w0 * rsqrtf(ratio);
    float ah = aw * ratio;
    float cx = (x + 0.5f) * s;
    float cy = (y + 0.5f) * s;

    float pcx = cx + d0 * 0.1f * aw;
    float pcy = cy + d1 * 0.1f * ah;
    float pw  = expf(d2 * 0.2f) * aw;
    float ph  = expf(d3 * 0.2f) * ah;

    float4 out4 = make_float4(pcx - 0.5f*pw, pcy - 0.5f*ph, pcx + 0.5f*pw, pcy + 0.5f*ph);
    size_t o = ((size_t)b*Atot + Aoff + (size_t)pos*9 + a);
    *(float4*)&boxes[o*4] = out4;
}

// ---------------------------------------------------------------------------
extern "C" void kernel_launch(void* const* d_in, const int* in_sizes, int n_in,
                              void* d_out, int out_size)
{
    static const int HS[5] = {64, 32, 16, 8, 4};
    static const int SS[5] = {8, 16, 32, 64, 128};

    // dynamic smem opt-in (no allocation; capture-legal host API)
    cudaFuncSetAttribute(conv3x3_k<true>,  cudaFuncAttributeMaxDynamicSharedMemorySize, SMEM_TOTAL);
    cudaFuncSetAttribute(conv3x3_k<false>, cudaFuncAttributeMaxDynamicSharedMemorySize, SMEM_TOTAL);

    const float* feat[5];
    const float *cw[5], *cbv[5], *rw[5], *rbv[5];
    for (int l = 0; l < 5; l++) feat[l] = (const float*)d_in[l];
    for (int i = 0; i < 5; i++) {
        cw[i]  = (const float*)d_in[5  + 2*i];
        cbv[i] = (const float*)d_in[6  + 2*i];
        rw[i]  = (const float*)d_in[15 + 2*i];
        rbv[i] = (const float*)d_in[16 + 2*i];
    }
    int B = in_sizes[0] / (256 * 64 * 64);

    float *buf0, *buf1, *headb;
    cudaGetSymbolAddress((void**)&buf0,  g_buf0);
    cudaGetSymbolAddress((void**)&buf1,  g_buf1);
    cudaGetSymbolAddress((void**)&headb, g_head);
    float* bufs[2] = {buf0, buf1};

    int Aoff[5], Atot = 0;
    for (int l = 0; l < 5; l++) { Aoff[l] = Atot; Atot += HS[l]*HS[l]*9; }

    float* out        = (float*)d_out;
    float* out_scores = out;
    float* out_cls    = out + (size_t)B * Atot;
    float* out_boxes  = out + (size_t)2 * B * Atot;

    for (int l = 0; l < 5; l++) {
        int H = HS[l], W = HS[l];
        int tilesX = (W + TW - 1) / TW;
        int tilesY = (H + TH - 1) / TH;
        dim3 grid(tilesX * tilesY, 4, B);
        dim3 gridCls(tilesX * tilesY, (720 + OCT - 1) / OCT, B);
        dim3 gridReg(tilesX * tilesY, 1, B);
        int total = B * 9 * H * W;
        int rblk  = (total + 255) / 256;

        // --- cls tower (compensated) ---
        const float* x = feat[l];
        for (int i = 0; i < 4; i++) {
            conv3x3_k<true><<<grid, 256, SMEM_TOTAL>>>(x, cw[i], cbv[i], bufs[i & 1], 256, H, W, tilesX, 1);
            x = bufs[i & 1];
        }
        conv3x3_k<true><<<gridCls, 256, SMEM_TOTAL>>>(x, cw[4], cbv[4], headb, 720, H, W, tilesX, 0);
        cls_reduce_k<<<rblk, 256>>>(headb, out_scores, out_cls, H, W, Aoff[l], Atot, total);

        // --- reg tower (plain) ---
        x = feat[l];
        for (int i = 0; i < 4; i++) {
            conv3x3_k<false><<<grid, 256, SMEM_TOTAL>>>(x, rw[i], rbv[i], bufs[i & 1], 256, H, W, tilesX, 1);
            x = bufs[i & 1];
        }
        conv3x3_k<false><<<gridReg, 256, SMEM_TOTAL>>>(x, rw[4], rbv[4], headb, 36, H, W, tilesX, 0);
        reg_decode_k<<<rblk, 256>>>(headb, out_boxes, H, W, SS[l], Aoff[l], Atot, total);
    }
    (void)n_in; (void)out_size;
}